// round 12
// baseline (speedup 1.0000x reference)
#include <cuda.h>
#include <cuda_runtime.h>
#include <cuda_fp16.h>
#include <cstdint>

// ============================================================================
// out = elu( (adj>0 ? (input@W)/cnt_row : 0) ), cnt_row = #(adj>0 in row);
// cnt==0 rows: softmax of all-(-9e15) is uniform 1/256.
// R12: R11 is L1-bound with occupancy capped by regs (3 CTAs). Remove the
//      A32 TMA->smem->LDS staging: convert reads GLOBAL directly (coalesced
//      LDG.128), packs fp16, STS to A16. Saves 64 smem-write wf/iter + all
//      A-mbarrier/TMA-A overhead. Freed smem -> 3-deep B ring. 56KB, 3 CTA/SM.
// ============================================================================

#define N_ROWS 200000
#define K_DIM  512
#define M_DIM  256
#define BM     64
#define BK     32
#define NITER  (K_DIM / BK)     // 16
#define THREADS 128             // 4 warps: 1 (m) x 4 (n), warp tile 64x64

// --- shared memory layout (bytes) --------------------------------------------
#define MBAR_B(s)  ((s) * 8)            // 0, 8, 16
#define MBAR_FD    24                   // frag-done, count 128
#define MASK_OFF   128                  // u32[64][8] -> 2176
#define CNT_OFF    (MASK_OFF + 64 * 8 * 4)      // int[64][2] -> 2688
#define A16_OFF    4096                 // 4KB (64 x 64B rows, SW64)
#define B_OFF(s)   (8192 + (s) * 16384) // 3 x 16KB (256 x 64B rows, SW64)
#define SMEM_TOTAL 57344                // 56KB -> 3 CTAs/SM
#define TXB        16384

// --- device scratch: W transposed to [M][K], fp16 RN --------------------------
__device__ __half g_Wh[M_DIM * K_DIM];

// ============================================================================
// helpers (plain sm_90-level PTX; no 'a' features)
// ============================================================================
__device__ __forceinline__ uint32_t smem_u32(const void* p) {
    uint32_t a;
    asm("{ .reg .u64 t; cvta.to.shared.u64 t, %1; cvt.u32.u64 %0, t; }"
        : "=r"(a) : "l"(p));
    return a;
}
#define MBARRIER_INIT(mbar, count) \
    asm volatile("mbarrier.init.shared.b64 [%0], %1;" \
        :: "r"((uint32_t)(mbar)), "r"((uint32_t)(count)) : "memory")
#define MBARRIER_EXPECT_TX(mbar, bytes) \
    asm volatile("mbarrier.arrive.expect_tx.shared.b64 _, [%0], %1;" \
        :: "r"((uint32_t)(mbar)), "r"((uint32_t)(bytes)) : "memory")
#define MBARRIER_ARRIVE(mbar) \
    asm volatile("mbarrier.arrive.release.cta.shared.b64 _, [%0];" \
        :: "r"((uint32_t)(mbar)) : "memory")
#define MBARRIER_WAIT_PARITY(mbar, parity) do { \
    uint32_t _mbar = (uint32_t)(mbar); \
    uint32_t _par = (uint32_t)(parity); \
    uint32_t _done; \
    asm volatile( \
        "{\n\t.reg .pred p;\n\t" \
        "mbarrier.try_wait.parity.acquire.cta.shared::cta.b64 p, [%1], %2;\n\t" \
        "selp.b32 %0, 1, 0, p;\n\t}" \
        : "=r"(_done) : "r"(_mbar), "r"(_par) : "memory"); \
    if (!_done) { \
        asm volatile( \
            "{\n\t.reg .pred P1;\n\t" \
            "WAIT_LOOP_%=:\n\t" \
            "mbarrier.try_wait.parity.acquire.cta.shared::cta.b64 P1, [%0], %1, 0x989680;\n\t" \
            "@P1 bra.uni WAIT_DONE_%=;\n\t" \
            "bra.uni WAIT_LOOP_%=;\n\t" \
            "WAIT_DONE_%=:\n\t}" \
            :: "r"(_mbar), "r"(_par) : "memory"); \
    } \
} while (0)
#define TMA_LOAD_2D(smem_addr, map_ptr, cx, cy, mbar) \
    asm volatile( \
        "cp.async.bulk.tensor.2d.shared::cta.global.tile.mbarrier::complete_tx::bytes " \
        "[%0], [%1, {%2, %3}], [%4];" \
        :: "r"((uint32_t)(smem_addr)), "l"(map_ptr), \
           "r"((int32_t)(cx)), "r"((int32_t)(cy)), "r"((uint32_t)(mbar)) \
        : "memory")

__device__ __forceinline__ void sts64(uint32_t a, uint32_t r0, uint32_t r1) {
    asm volatile("st.shared.v2.b32 [%0], {%1,%2};"
                 :: "r"(a), "r"(r0), "r"(r1) : "memory");
}
__device__ __forceinline__ void ldsm_x4(uint32_t* r, uint32_t addr) {
    asm volatile("ldmatrix.sync.aligned.m8n8.x4.shared.b16 {%0,%1,%2,%3}, [%4];"
                 : "=r"(r[0]), "=r"(r[1]), "=r"(r[2]), "=r"(r[3]) : "r"(addr));
}
__device__ __forceinline__ uint32_t packh2(float lo, float hi) {
    uint32_t d;
    asm("cvt.rn.f16x2.f32 %0, %1, %2;" : "=r"(d) : "f"(hi), "f"(lo));
    return d;
}
__device__ __forceinline__ void mma16816(float* c, const uint32_t* a,
                                         const uint32_t* b) {
    asm volatile(
        "mma.sync.aligned.m16n8k16.row.col.f32.f16.f16.f32 "
        "{%0,%1,%2,%3}, {%4,%5,%6,%7}, {%8,%9}, {%0,%1,%2,%3};"
        : "+f"(c[0]), "+f"(c[1]), "+f"(c[2]), "+f"(c[3])
        : "r"(a[0]), "r"(a[1]), "r"(a[2]), "r"(a[3]), "r"(b[0]), "r"(b[1]));
}

// ============================================================================
// prep: W [K=512, M=256] row-major fp32 -> g_Wh [M][K] fp16 (RN)
// ============================================================================
__global__ void prep_wh_kernel(const float* __restrict__ W) {
    int idx = blockIdx.x * blockDim.x + threadIdx.x;
    int k = idx >> 8;
    int m = idx & 255;
    g_Wh[m * K_DIM + k] = __float2half_rn(W[idx]);
}

// ============================================================================
// fused GEMM (global-direct convert + TMA-B + ldmatrix + mma.sync) + attention
// ============================================================================
__global__ void __launch_bounds__(THREADS, 3) gat_kernel(
    const __grid_constant__ CUtensorMap tmap_b,
    const float* __restrict__ inp,
    const int* __restrict__ adj,
    float* __restrict__ out)
{
    extern __shared__ char smem[];
    const uint32_t sb = smem_u32(smem);
    uint32_t* smask = (uint32_t*)(smem + MASK_OFF);   // [64][8]
    int* scnt = (int*)(smem + CNT_OFF);               // [64][2]

    const int tid  = threadIdx.x;
    const int lane = tid & 31;
    const int wn   = tid >> 5;   // 0..3 : 64-col band (single m-band)
    const int tile = blockIdx.x * BM;

    // ---- mbarrier init + TMA-B prologue (3-deep ring) ---------------------------
    if (tid == 0) {
        MBARRIER_INIT(sb + MBAR_B(0), 1);
        MBARRIER_INIT(sb + MBAR_B(1), 1);
        MBARRIER_INIT(sb + MBAR_B(2), 1);
        MBARRIER_INIT(sb + MBAR_FD, THREADS);
    }
    __syncthreads();
    if (tid == 0) {
        #pragma unroll
        for (int j = 0; j < 3; j++) {
            MBARRIER_EXPECT_TX(sb + MBAR_B(j), TXB);
            TMA_LOAD_2D(sb + B_OFF(j), &tmap_b, j * BK, 0, sb + MBAR_B(j));
        }
    }

    // ---- adj mask + count (overlaps TMA flight; 64 | N_ROWS) -------------------
    {
        int r = tid >> 1;            // 0..63
        int h = tid & 1;             // 128-col half
        const int4* ap = (const int4*)(adj + (size_t)(tile + r) * M_DIM + h * 128);
        int cnt = 0;
        #pragma unroll
        for (int g = 0; g < 4; g++) {
            uint32_t m = 0;
            #pragma unroll
            for (int w = 0; w < 8; w++) {
                int4 v = __ldg(ap + g * 8 + w);
                m |= (v.x > 0 ? 1u : 0u) << (w * 4 + 0);
                m |= (v.y > 0 ? 1u : 0u) << (w * 4 + 1);
                m |= (v.z > 0 ? 1u : 0u) << (w * 4 + 2);
                m |= (v.w > 0 ? 1u : 0u) << (w * 4 + 3);
            }
            smask[r * 8 + h * 4 + g] = m;
            cnt += __popc(m);
        }
        scnt[r * 2 + h] = cnt;
    }

    // ---- per-thread constants ----------------------------------------------------
    const int arow = lane >> 2;                 // 0..7 (epilogue)

    // convert mapping (global-direct): thread t covers rows (t>>3)+16g, g=0..3,
    // 16B (4 floats) at byte (t&7)*16 of each 128B chunk-row -> coalesced LDG.128.
    const int crow0 = tid >> 3;                 // 0..15
    const int cseg  = tid & 7;                  // 16B segment
    const float4* cgp = (const float4*)(inp + (size_t)(tile + crow0) * K_DIM) + cseg;
    // dest: A16 row crow0+16g at 64B rows, SW64 xor constant across g
    const uint32_t cxor = (uint32_t)((crow0 >> 1) & 3) << 4;
    const uint32_t cdst = sb + A16_OFF + (uint32_t)crow0 * 64 +
                          (((uint32_t)cseg * 8) ^ cxor);

    // ldmatrix lane addressing (SW64: unit ^= (row>>1)&3)
    const uint32_t l7 = lane & 7;
    const uint32_t sw64x = ((l7 >> 1) & 3) << 4;
    const uint32_t a_row = l7 + ((lane >> 3) & 1) * 8;
    const uint32_t a_kseg = (lane >> 4) & 1;
    const uint32_t a_base = sb + A16_OFF + a_row * 64;
    const uint32_t b_row = (uint32_t)(wn * 64) + l7 + ((lane >> 4) & 1) * 8;
    const uint32_t b_kseg = (lane >> 3) & 1;
    const uint32_t b_base_off = b_row * 64;

    float c[4][8][4];
    #pragma unroll
    for (int mf = 0; mf < 4; mf++)
        #pragma unroll
        for (int nf = 0; nf < 8; nf++)
            #pragma unroll
            for (int e = 0; e < 4; e++) c[mf][nf][e] = 0.0f;

    // ---- prologue convert: chunk 0 -> A16 (direct from global) --------------------
    {
        #pragma unroll
        for (int g = 0; g < 4; g++) {
            float4 f = __ldg(cgp + (size_t)g * 16 * (K_DIM / 4));
            sts64(cdst + (uint32_t)g * 1024, packh2(f.x, f.y), packh2(f.z, f.w));
        }
    }
    __syncthreads();   // A16(chunk0) visible

    int bs = 0, bsph = 0;   // B ring cursor

    // ---- mainloop: 16 x BK=32 -------------------------------------------------------
    #pragma unroll 1
    for (int i = 0; i < NITER; i++) {
        // phase 1: MMAs on chunk i
        MBARRIER_WAIT_PARITY(sb + MBAR_B(bs), (uint32_t)bsph);
        {
            const uint32_t bB = sb + B_OFF(bs) + b_base_off;
            #pragma unroll
            for (int ks = 0; ks < 2; ks++) {
                const uint32_t ak = (((uint32_t)ks * 2 + a_kseg) << 4) ^ sw64x;
                const uint32_t bk = (((uint32_t)ks * 2 + b_kseg) << 4) ^ sw64x;
                uint32_t ra[4][4];
                #pragma unroll
                for (int mf = 0; mf < 4; mf++)
                    ldsm_x4(ra[mf], a_base + (uint32_t)mf * 1024 + ak);
                #pragma unroll
                for (int np = 0; np < 4; np++) {
                    uint32_t rb[4];
                    ldsm_x4(rb, bB + (uint32_t)np * 1024 + bk);
                    #pragma unroll
                    for (int mf = 0; mf < 4; mf++) {
                        mma16816(c[mf][np * 2 + 0], ra[mf], rb);
                        mma16816(c[mf][np * 2 + 1], ra[mf], rb + 2);
                    }
                }
            }
        }
        MBARRIER_ARRIVE(sb + MBAR_FD);   // my A16 + B[bs] reads complete

        // phase 2: convert chunk i+1 (LDG issued before FD wait -> latency overlap)
        if (i + 1 < NITER) {
            const float4* gp = cgp + (size_t)(i + 1) * (BK / 4);
            float4 f0 = __ldg(gp);
            float4 f1 = __ldg(gp + (size_t)16 * (K_DIM / 4));
            float4 f2 = __ldg(gp + (size_t)32 * (K_DIM / 4));
            float4 f3 = __ldg(gp + (size_t)48 * (K_DIM / 4));
            uint32_t h0 = packh2(f0.x, f0.y), h1 = packh2(f0.z, f0.w);
            uint32_t h2 = packh2(f1.x, f1.y), h3 = packh2(f1.z, f1.w);
            uint32_t h4 = packh2(f2.x, f2.y), h5 = packh2(f2.z, f2.w);
            uint32_t h6 = packh2(f3.x, f3.y), h7 = packh2(f3.z, f3.w);
            // wait all CTA threads finished reading A16(chunk i)
            MBARRIER_WAIT_PARITY(sb + MBAR_FD, (uint32_t)(i & 1));
            sts64(cdst,        h0, h1);
            sts64(cdst + 1024, h2, h3);
            sts64(cdst + 2048, h4, h5);
            sts64(cdst + 3072, h6, h7);
        }
        __syncthreads();   // A16(chunk i+1) visible; B[bs] free

        // refill B chunk i+3 into the slot just consumed
        if (tid == 0 && i + 3 < NITER) {
            MBARRIER_EXPECT_TX(sb + MBAR_B(bs), TXB);
            TMA_LOAD_2D(sb + B_OFF(bs), &tmap_b, (i + 3) * BK, 0, sb + MBAR_B(bs));
        }
        if (++bs == 3) { bs = 0; bsph ^= 1; }
    }

    // ---- epilogue: scale by 1/cnt on mask, elu, store -------------------------------
    #pragma unroll
    for (int mf = 0; mf < 4; mf++) {
        const int r0 = mf * 16 + arow;
        #pragma unroll
        for (int half = 0; half < 2; half++) {
            const int rr = r0 + half * 8;
            const int grow = tile + rr;
            const int cnt = scnt[rr * 2] + scnt[rr * 2 + 1];
            const bool all_on = (cnt == 0);
            const float scale = all_on ? (1.0f / 256.0f) : (1.0f / (float)cnt);
            #pragma unroll
            for (int nf = 0; nf < 8; nf++) {
                const int col = wn * 64 + nf * 8 + (int)(lane & 3) * 2;
                const uint32_t mw = smask[rr * 8 + (col >> 5)];
                float2 o;
                #pragma unroll
                for (int e = 0; e < 2; e++) {
                    float h = c[mf][nf][half * 2 + e];
                    bool on = all_on | (((mw >> ((col + e) & 31)) & 1u) != 0u);
                    float v = on ? h * scale : 0.0f;
                    float res = (v > 0.0f) ? v : (__expf(v) - 1.0f);
                    ((float*)&o)[e] = res;
                }
                *(float2*)(out + (size_t)grow * M_DIM + col) = o;
            }
        }
    }
}

// ============================================================================
// host launch
// ============================================================================
typedef CUresult (*EncodeTiledFn)(
    CUtensorMap*, CUtensorMapDataType, cuuint32_t, void*,
    const cuuint64_t*, const cuuint64_t*, const cuuint32_t*, const cuuint32_t*,
    CUtensorMapInterleave, CUtensorMapSwizzle, CUtensorMapL2promotion,
    CUtensorMapFloatOOBfill);

extern "C" void kernel_launch(void* const* d_in, const int* in_sizes, int n_in,
                              void* d_out, int out_size) {
    const float* inp = (const float*)d_in[0];
    const int*   adj = (const int*)d_in[1];
    const float* W   = (const float*)d_in[2];
    // d_in[3] ('a') provably cancels in the softmax; unused.
    float* out = (float*)d_out;

    prep_wh_kernel<<<(K_DIM * M_DIM) / 256, 256>>>(W);

    void* wh_ptr = nullptr;
    cudaGetSymbolAddress(&wh_ptr, g_Wh);

    void* fp = nullptr;
    cudaDriverEntryPointQueryResult qres;
    cudaGetDriverEntryPointByVersion("cuTensorMapEncodeTiled", &fp, 12000,
                                     cudaEnableDefault, &qres);
    EncodeTiledFn enc = (EncodeTiledFn)fp;

    alignas(64) CUtensorMap tmB;
    {
        cuuint64_t dims[2]    = {(cuuint64_t)K_DIM, (cuuint64_t)M_DIM};
        cuuint64_t strides[1] = {(cuuint64_t)K_DIM * sizeof(__half)};
        cuuint32_t box[2]     = {32u, (cuuint32_t)M_DIM};   // 64B x 256 rows
        cuuint32_t es[2]      = {1, 1};
        enc(&tmB, CU_TENSOR_MAP_DATA_TYPE_FLOAT16, 2, wh_ptr,
            dims, strides, box, es,
            CU_TENSOR_MAP_INTERLEAVE_NONE, CU_TENSOR_MAP_SWIZZLE_64B,
            CU_TENSOR_MAP_L2_PROMOTION_L2_128B, CU_TENSOR_MAP_FLOAT_OOB_FILL_NONE);
    }

    static bool attr_set = false;
    if (!attr_set) {
        cudaFuncSetAttribute(gat_kernel,
                             cudaFuncAttributeMaxDynamicSharedMemorySize,
                             SMEM_TOTAL);
        attr_set = true;
    }
    const int grid = N_ROWS / BM;   // 3125 (exact)
    gat_kernel<<<grid, THREADS, SMEM_TOTAL>>>(tmB, inp, adj, out);
}

// round 13
// speedup vs baseline: 1.0519x; 1.0519x over previous
#include <cuda.h>
#include <cuda_runtime.h>
#include <cuda_fp16.h>
#include <cstdint>

// ============================================================================
// out = elu( (adj>0 ? (input@W)/cnt_row : 0) ), cnt_row = #(adj>0 in row);
// cnt==0 rows: softmax of all-(-9e15) is uniform 1/256.
// R13: R12 (LDG-direct convert) regressed — exposed DRAM latency; reverted.
//      R11 + A16 DOUBLE buffer: convert(i+1) writes buf (i+1)&1 while MMA read
//      buf i&1, so the frag-done mbarrier is deleted (ordering comes free from
//      the per-iter __syncthreads). 68KB smem, still 3 CTAs/SM.
// ============================================================================

#define N_ROWS 200000
#define K_DIM  512
#define M_DIM  256
#define BM     64
#define BK     32
#define NITER  (K_DIM / BK)     // 16
#define THREADS 128             // 4 warps: 1 (m) x 4 (n), warp tile 64x64

// --- shared memory layout (bytes) --------------------------------------------
#define MBAR_A(s)  ((s) * 8)            // 0, 8, 16
#define MBAR_B(s)  (24 + (s) * 8)       // 24, 32
#define MASK_OFF   128                  // u32[64][8] -> 2176
#define CNT_OFF    (MASK_OFF + 64 * 8 * 4)      // int[64][2] -> 2688
#define A16_OFF    4096                 // 2 x 4KB (64 x 64B rows, SW64) -> 12288
#define A32_OFF(s) (12288 + (s) * 8192) // 3 x 8KB (64 x 128B rows, SW128) -> 36864
#define B_OFF(s)   (36864 + (s) * 16384) // 2 x 16KB (256 x 64B rows, SW64) -> 69632
#define SMEM_TOTAL 69632                // 68KB -> 3 CTAs/SM
#define TXA        8192
#define TXB        16384

// --- device scratch: W transposed to [M][K], fp16 RN --------------------------
__device__ __half g_Wh[M_DIM * K_DIM];

// ============================================================================
// helpers (plain sm_90-level PTX; no 'a' features)
// ============================================================================
__device__ __forceinline__ uint32_t smem_u32(const void* p) {
    uint32_t a;
    asm("{ .reg .u64 t; cvta.to.shared.u64 t, %1; cvt.u32.u64 %0, t; }"
        : "=r"(a) : "l"(p));
    return a;
}
#define MBARRIER_INIT(mbar, count) \
    asm volatile("mbarrier.init.shared.b64 [%0], %1;" \
        :: "r"((uint32_t)(mbar)), "r"((uint32_t)(count)) : "memory")
#define MBARRIER_EXPECT_TX(mbar, bytes) \
    asm volatile("mbarrier.arrive.expect_tx.shared.b64 _, [%0], %1;" \
        :: "r"((uint32_t)(mbar)), "r"((uint32_t)(bytes)) : "memory")
#define MBARRIER_WAIT_PARITY(mbar, parity) do { \
    uint32_t _mbar = (uint32_t)(mbar); \
    uint32_t _par = (uint32_t)(parity); \
    uint32_t _done; \
    asm volatile( \
        "{\n\t.reg .pred p;\n\t" \
        "mbarrier.try_wait.parity.acquire.cta.shared::cta.b64 p, [%1], %2;\n\t" \
        "selp.b32 %0, 1, 0, p;\n\t}" \
        : "=r"(_done) : "r"(_mbar), "r"(_par) : "memory"); \
    if (!_done) { \
        asm volatile( \
            "{\n\t.reg .pred P1;\n\t" \
            "WAIT_LOOP_%=:\n\t" \
            "mbarrier.try_wait.parity.acquire.cta.shared::cta.b64 P1, [%0], %1, 0x989680;\n\t" \
            "@P1 bra.uni WAIT_DONE_%=;\n\t" \
            "bra.uni WAIT_LOOP_%=;\n\t" \
            "WAIT_DONE_%=:\n\t}" \
            :: "r"(_mbar), "r"(_par) : "memory"); \
    } \
} while (0)
#define TMA_LOAD_2D(smem_addr, map_ptr, cx, cy, mbar) \
    asm volatile( \
        "cp.async.bulk.tensor.2d.shared::cta.global.tile.mbarrier::complete_tx::bytes " \
        "[%0], [%1, {%2, %3}], [%4];" \
        :: "r"((uint32_t)(smem_addr)), "l"(map_ptr), \
           "r"((int32_t)(cx)), "r"((int32_t)(cy)), "r"((uint32_t)(mbar)) \
        : "memory")

__device__ __forceinline__ float4 lds128f(uint32_t a) {
    float4 v;
    asm volatile("ld.shared.v4.f32 {%0,%1,%2,%3}, [%4];"
                 : "=f"(v.x), "=f"(v.y), "=f"(v.z), "=f"(v.w) : "r"(a));
    return v;
}
__device__ __forceinline__ void sts128(uint32_t a, uint32_t r0, uint32_t r1,
                                       uint32_t r2, uint32_t r3) {
    asm volatile("st.shared.v4.b32 [%0], {%1,%2,%3,%4};"
                 :: "r"(a), "r"(r0), "r"(r1), "r"(r2), "r"(r3) : "memory");
}
__device__ __forceinline__ void ldsm_x4(uint32_t* r, uint32_t addr) {
    asm volatile("ldmatrix.sync.aligned.m8n8.x4.shared.b16 {%0,%1,%2,%3}, [%4];"
                 : "=r"(r[0]), "=r"(r[1]), "=r"(r[2]), "=r"(r[3]) : "r"(addr));
}
__device__ __forceinline__ uint32_t packh2(float lo, float hi) {
    uint32_t d;
    asm("cvt.rn.f16x2.f32 %0, %1, %2;" : "=r"(d) : "f"(hi), "f"(lo));
    return d;
}
__device__ __forceinline__ void mma16816(float* c, const uint32_t* a,
                                         const uint32_t* b) {
    asm volatile(
        "mma.sync.aligned.m16n8k16.row.col.f32.f16.f16.f32 "
        "{%0,%1,%2,%3}, {%4,%5,%6,%7}, {%8,%9}, {%0,%1,%2,%3};"
        : "+f"(c[0]), "+f"(c[1]), "+f"(c[2]), "+f"(c[3])
        : "r"(a[0]), "r"(a[1]), "r"(a[2]), "r"(a[3]), "r"(b[0]), "r"(b[1]));
}

// ============================================================================
// prep: W [K=512, M=256] row-major fp32 -> g_Wh [M][K] fp16 (RN)
// ============================================================================
__global__ void prep_wh_kernel(const float* __restrict__ W) {
    int idx = blockIdx.x * blockDim.x + threadIdx.x;
    int k = idx >> 8;
    int m = idx & 255;
    g_Wh[m * K_DIM + k] = __float2half_rn(W[idx]);
}

// ============================================================================
// fused GEMM (TMA + double-buffered convert + ldmatrix + mma.sync) + attention
// ============================================================================
__global__ void __launch_bounds__(THREADS, 3) gat_kernel(
    const __grid_constant__ CUtensorMap tmap_a,
    const __grid_constant__ CUtensorMap tmap_b,
    const int* __restrict__ adj,
    float* __restrict__ out)
{
    extern __shared__ char smem[];
    const uint32_t sb = smem_u32(smem);
    uint32_t* smask = (uint32_t*)(smem + MASK_OFF);   // [64][8]
    int* scnt = (int*)(smem + CNT_OFF);               // [64][2]

    const int tid  = threadIdx.x;
    const int lane = tid & 31;
    const int wn   = tid >> 5;   // 0..3 : 64-col band (single m-band)
    const int tile = blockIdx.x * BM;

    // ---- mbarrier init + TMA prologue -----------------------------------------
    if (tid == 0) {
        MBARRIER_INIT(sb + MBAR_A(0), 1);
        MBARRIER_INIT(sb + MBAR_A(1), 1);
        MBARRIER_INIT(sb + MBAR_A(2), 1);
        MBARRIER_INIT(sb + MBAR_B(0), 1);
        MBARRIER_INIT(sb + MBAR_B(1), 1);
    }
    __syncthreads();
    if (tid == 0) {
        #pragma unroll
        for (int j = 0; j < 3; j++) {
            MBARRIER_EXPECT_TX(sb + MBAR_A(j), TXA);
            TMA_LOAD_2D(sb + A32_OFF(j), &tmap_a, j * BK, tile, sb + MBAR_A(j));
        }
        #pragma unroll
        for (int j = 0; j < 2; j++) {
            MBARRIER_EXPECT_TX(sb + MBAR_B(j), TXB);
            TMA_LOAD_2D(sb + B_OFF(j), &tmap_b, j * BK, 0, sb + MBAR_B(j));
        }
    }

    // ---- adj mask + count (overlaps TMA flight; 64 | N_ROWS) -------------------
    {
        int r = tid >> 1;            // 0..63
        int h = tid & 1;             // 128-col half
        const int4* ap = (const int4*)(adj + (size_t)(tile + r) * M_DIM + h * 128);
        int cnt = 0;
        #pragma unroll
        for (int g = 0; g < 4; g++) {
            uint32_t m = 0;
            #pragma unroll
            for (int w = 0; w < 8; w++) {
                int4 v = __ldg(ap + g * 8 + w);
                m |= (v.x > 0 ? 1u : 0u) << (w * 4 + 0);
                m |= (v.y > 0 ? 1u : 0u) << (w * 4 + 1);
                m |= (v.z > 0 ? 1u : 0u) << (w * 4 + 2);
                m |= (v.w > 0 ? 1u : 0u) << (w * 4 + 3);
            }
            smask[r * 8 + h * 4 + g] = m;
            cnt += __popc(m);
        }
        scnt[r * 2 + h] = cnt;
    }

    // ---- per-thread constants ----------------------------------------------------
    const int arow = lane >> 2;                 // 0..7 (epilogue)

    // convert mapping: row cr = tid>>1 (0..63), k-half sub = tid&1
    const int cr  = tid >> 1;
    const int sub = tid & 1;
    const uint32_t xr128 = (uint32_t)(cr & 7) << 4;        // src SW128 xor
    const uint32_t xr64  = (uint32_t)((cr >> 1) & 3) << 4; // dst SW64 xor
    const uint32_t csrc_row = (uint32_t)cr * 128;          // + A32_OFF(slot)
    const uint32_t csu = (uint32_t)sub * 4;                // src 16B-unit base
    const uint32_t cdst_base = sb + A16_OFF + (uint32_t)cr * 64;
    const uint32_t cdu = (uint32_t)sub * 2;                // dst 16B-unit base

    // ldmatrix lane addressing (SW64: unit ^= (row>>1)&3)
    const uint32_t l7 = lane & 7;
    const uint32_t sw64x = ((l7 >> 1) & 3) << 4;
    const uint32_t a_row = l7 + ((lane >> 3) & 1) * 8;
    const uint32_t a_kseg = (lane >> 4) & 1;
    const uint32_t a_base0 = sb + A16_OFF + a_row * 64;
    const uint32_t b_row = (uint32_t)(wn * 64) + l7 + ((lane >> 4) & 1) * 8;
    const uint32_t b_kseg = (lane >> 3) & 1;
    const uint32_t b_base_off = b_row * 64;

    float c[4][8][4];
    #pragma unroll
    for (int mf = 0; mf < 4; mf++)
        #pragma unroll
        for (int nf = 0; nf < 8; nf++)
            #pragma unroll
            for (int e = 0; e < 4; e++) c[mf][nf][e] = 0.0f;

    // ---- prologue convert: chunk 0 -> A16 buf 0 -----------------------------------
    MBARRIER_WAIT_PARITY(sb + MBAR_A(0), 0);
    {
        const uint32_t src = sb + A32_OFF(0) + csrc_row;
        float4 f0 = lds128f(src + (((csu + 0) << 4) ^ xr128));
        float4 f1 = lds128f(src + (((csu + 1) << 4) ^ xr128));
        float4 f2 = lds128f(src + (((csu + 2) << 4) ^ xr128));
        float4 f3 = lds128f(src + (((csu + 3) << 4) ^ xr128));
        sts128(cdst_base + (((cdu + 0) << 4) ^ xr64),
               packh2(f0.x, f0.y), packh2(f0.z, f0.w),
               packh2(f1.x, f1.y), packh2(f1.z, f1.w));
        sts128(cdst_base + (((cdu + 1) << 4) ^ xr64),
               packh2(f2.x, f2.y), packh2(f2.z, f2.w),
               packh2(f3.x, f3.y), packh2(f3.z, f3.w));
    }
    __syncthreads();   // A16 buf0 (chunk0) visible

    // convert slot/phase counters (for chunk j = i+1, starting j=1)
    int ca_slot = 1, ca_ph = 0;
    // refill slot counter for chunk j = i+3 (starting j=3 -> slot 0)
    int rf_slot = 0;

    // ---- mainloop: 16 x BK=32 -------------------------------------------------------
    #pragma unroll 1
    for (int i = 0; i < NITER; i++) {
        // phase 1: MMAs on chunk i from A16 buf i&1
        MBARRIER_WAIT_PARITY(sb + MBAR_B(i & 1), (uint32_t)((i >> 1) & 1));
        {
            const uint32_t aB = a_base0 + (uint32_t)(i & 1) * 4096;
            const uint32_t bB = sb + B_OFF(i & 1) + b_base_off;
            #pragma unroll
            for (int ks = 0; ks < 2; ks++) {
                const uint32_t ak = (((uint32_t)ks * 2 + a_kseg) << 4) ^ sw64x;
                const uint32_t bk = (((uint32_t)ks * 2 + b_kseg) << 4) ^ sw64x;
                uint32_t ra[4][4];
                #pragma unroll
                for (int mf = 0; mf < 4; mf++)
                    ldsm_x4(ra[mf], aB + (uint32_t)mf * 1024 + ak);
                #pragma unroll
                for (int np = 0; np < 4; np++) {
                    uint32_t rb[4];
                    ldsm_x4(rb, bB + (uint32_t)np * 1024 + bk);
                    #pragma unroll
                    for (int mf = 0; mf < 4; mf++) {
                        mma16816(c[mf][np * 2 + 0], ra[mf], rb);
                        mma16816(c[mf][np * 2 + 1], ra[mf], rb + 2);
                    }
                }
            }
        }

        // phase 2: convert chunk i+1 into A16 buf (i+1)&1 (no FD barrier needed:
        // readers of this buffer retired at the END of iteration i-1's sync)
        if (i + 1 < NITER) {
            MBARRIER_WAIT_PARITY(sb + MBAR_A(ca_slot), (uint32_t)ca_ph);
            const uint32_t src = sb + A32_OFF(ca_slot) + csrc_row;
            const uint32_t cdst = cdst_base + (uint32_t)((i + 1) & 1) * 4096;
            float4 f0 = lds128f(src + (((csu + 0) << 4) ^ xr128));
            float4 f1 = lds128f(src + (((csu + 1) << 4) ^ xr128));
            float4 f2 = lds128f(src + (((csu + 2) << 4) ^ xr128));
            float4 f3 = lds128f(src + (((csu + 3) << 4) ^ xr128));
            sts128(cdst + (((cdu + 0) << 4) ^ xr64),
                   packh2(f0.x, f0.y), packh2(f0.z, f0.w),
                   packh2(f1.x, f1.y), packh2(f1.z, f1.w));
            sts128(cdst + (((cdu + 1) << 4) ^ xr64),
                   packh2(f2.x, f2.y), packh2(f2.z, f2.w),
                   packh2(f3.x, f3.y), packh2(f3.z, f3.w));
            if (++ca_slot == 3) { ca_slot = 0; ca_ph ^= 1; }
        }
        __syncthreads();   // A16 buf (i+1)&1 visible; A32[old] + B[i&1] free

        // refills: A chunk i+3 into slot rf_slot, B chunk i+2 into slot i&1
        if (tid == 0) {
            if (i + 3 < NITER) {
                MBARRIER_EXPECT_TX(sb + MBAR_A(rf_slot), TXA);
                TMA_LOAD_2D(sb + A32_OFF(rf_slot), &tmap_a, (i + 3) * BK, tile,
                            sb + MBAR_A(rf_slot));
            }
            if (i + 2 < NITER) {
                MBARRIER_EXPECT_TX(sb + MBAR_B(i & 1), TXB);
                TMA_LOAD_2D(sb + B_OFF(i & 1), &tmap_b, (i + 2) * BK, 0,
                            sb + MBAR_B(i & 1));
            }
        }
        if (++rf_slot == 3) rf_slot = 0;
    }

    // ---- epilogue: scale by 1/cnt on mask, elu, store -------------------------------
    #pragma unroll
    for (int mf = 0; mf < 4; mf++) {
        const int r0 = mf * 16 + arow;
        #pragma unroll
        for (int half = 0; half < 2; half++) {
            const int rr = r0 + half * 8;
            const int grow = tile + rr;
            const int cnt = scnt[rr * 2] + scnt[rr * 2 + 1];
            const bool all_on = (cnt == 0);
            const float scale = all_on ? (1.0f / 256.0f) : (1.0f / (float)cnt);
            #pragma unroll
            for (int nf = 0; nf < 8; nf++) {
                const int col = wn * 64 + nf * 8 + (int)(lane & 3) * 2;
                const uint32_t mw = smask[rr * 8 + (col >> 5)];
                float2 o;
                #pragma unroll
                for (int e = 0; e < 2; e++) {
                    float h = c[mf][nf][half * 2 + e];
                    bool on = all_on | (((mw >> ((col + e) & 31)) & 1u) != 0u);
                    float v = on ? h * scale : 0.0f;
                    float res = (v > 0.0f) ? v : (__expf(v) - 1.0f);
                    ((float*)&o)[e] = res;
                }
                *(float2*)(out + (size_t)grow * M_DIM + col) = o;
            }
        }
    }
}

// ============================================================================
// host launch
// ============================================================================
typedef CUresult (*EncodeTiledFn)(
    CUtensorMap*, CUtensorMapDataType, cuuint32_t, void*,
    const cuuint64_t*, const cuuint64_t*, const cuuint32_t*, const cuuint32_t*,
    CUtensorMapInterleave, CUtensorMapSwizzle, CUtensorMapL2promotion,
    CUtensorMapFloatOOBfill);

extern "C" void kernel_launch(void* const* d_in, const int* in_sizes, int n_in,
                              void* d_out, int out_size) {
    const float* inp = (const float*)d_in[0];
    const int*   adj = (const int*)d_in[1];
    const float* W   = (const float*)d_in[2];
    // d_in[3] ('a') provably cancels in the softmax; unused.
    float* out = (float*)d_out;

    prep_wh_kernel<<<(K_DIM * M_DIM) / 256, 256>>>(W);

    void* wh_ptr = nullptr;
    cudaGetSymbolAddress(&wh_ptr, g_Wh);

    void* fp = nullptr;
    cudaDriverEntryPointQueryResult qres;
    cudaGetDriverEntryPointByVersion("cuTensorMapEncodeTiled", &fp, 12000,
                                     cudaEnableDefault, &qres);
    EncodeTiledFn enc = (EncodeTiledFn)fp;

    alignas(64) CUtensorMap tmA;
    alignas(64) CUtensorMap tmB;
    {
        cuuint64_t dims[2]    = {(cuuint64_t)K_DIM, (cuuint64_t)N_ROWS};
        cuuint64_t strides[1] = {(cuuint64_t)K_DIM * sizeof(float)};
        cuuint32_t box[2]     = {32u, (cuuint32_t)BM};      // 128B x 64 rows
        cuuint32_t es[2]      = {1, 1};
        enc(&tmA, CU_TENSOR_MAP_DATA_TYPE_FLOAT32, 2, (void*)inp,
            dims, strides, box, es,
            CU_TENSOR_MAP_INTERLEAVE_NONE, CU_TENSOR_MAP_SWIZZLE_128B,
            CU_TENSOR_MAP_L2_PROMOTION_L2_128B, CU_TENSOR_MAP_FLOAT_OOB_FILL_NONE);
    }
    {
        cuuint64_t dims[2]    = {(cuuint64_t)K_DIM, (cuuint64_t)M_DIM};
        cuuint64_t strides[1] = {(cuuint64_t)K_DIM * sizeof(__half)};
        cuuint32_t box[2]     = {32u, (cuuint32_t)M_DIM};   // 64B x 256 rows
        cuuint32_t es[2]      = {1, 1};
        enc(&tmB, CU_TENSOR_MAP_DATA_TYPE_FLOAT16, 2, wh_ptr,
            dims, strides, box, es,
            CU_TENSOR_MAP_INTERLEAVE_NONE, CU_TENSOR_MAP_SWIZZLE_64B,
            CU_TENSOR_MAP_L2_PROMOTION_L2_128B, CU_TENSOR_MAP_FLOAT_OOB_FILL_NONE);
    }

    static bool attr_set = false;
    if (!attr_set) {
        cudaFuncSetAttribute(gat_kernel,
                             cudaFuncAttributeMaxDynamicSharedMemorySize,
                             SMEM_TOTAL);
        attr_set = true;
    }
    const int grid = N_ROWS / BM;   // 3125 (exact)
    gat_kernel<<<grid, THREADS, SMEM_TOTAL>>>(tmA, tmB, adj, out);
}

// round 14
// speedup vs baseline: 1.0700x; 1.0172x over previous
#include <cuda.h>
#include <cuda_runtime.h>
#include <cuda_fp16.h>
#include <cstdint>

// ============================================================================
// out = elu( (adj>0 ? (input@W)/cnt_row : 0) ), cnt_row = #(adj>0 in row);
// cnt==0 rows: softmax of all-(-9e15) is uniform 1/256.
// R14: R13 (A16 double-buffer) regressed; R11=203us is reference. Now delete
//      the A16 intermediate ENTIRELY: A fragments are built straight from the
//      fp32 SW128 tile via LDS.64 + cvt.rn.f16x2 in registers (conflict-free).
//      Removes convert stage, FD barrier, A16 tile; loop = waitA, waitB,
//      lds/cvt/ldsm/mma, sync, refill. 60KB smem, 3 CTAs/SM.
// ============================================================================

#define N_ROWS 200000
#define K_DIM  512
#define M_DIM  256
#define BM     64
#define BK     32
#define NITER  (K_DIM / BK)     // 16
#define THREADS 128             // 4 warps: 1 (m) x 4 (n), warp tile 64x64

// --- shared memory layout (bytes) --------------------------------------------
#define MBAR_A(s)  ((s) * 8)            // 0, 8, 16
#define MBAR_B(s)  (24 + (s) * 8)       // 24, 32
#define MASK_OFF   128                  // u32[64][8] -> 2176
#define CNT_OFF    (MASK_OFF + 64 * 8 * 4)      // int[64][2] -> 2688
#define A32_OFF(s) (4096 + (s) * 8192)  // 3 x 8KB (64 x 128B rows, SW128) -> 28672
#define B_OFF(s)   (28672 + (s) * 16384) // 2 x 16KB (256 x 64B rows, SW64) -> 61440
#define SMEM_TOTAL 61440                // 60KB -> 3 CTAs/SM
#define TXA        8192
#define TXB        16384

// --- device scratch: W transposed to [M][K], fp16 RN --------------------------
__device__ __half g_Wh[M_DIM * K_DIM];

// ============================================================================
// helpers (plain sm_90-level PTX; no 'a' features)
// ============================================================================
__device__ __forceinline__ uint32_t smem_u32(const void* p) {
    uint32_t a;
    asm("{ .reg .u64 t; cvta.to.shared.u64 t, %1; cvt.u32.u64 %0, t; }"
        : "=r"(a) : "l"(p));
    return a;
}
#define MBARRIER_INIT(mbar, count) \
    asm volatile("mbarrier.init.shared.b64 [%0], %1;" \
        :: "r"((uint32_t)(mbar)), "r"((uint32_t)(count)) : "memory")
#define MBARRIER_EXPECT_TX(mbar, bytes) \
    asm volatile("mbarrier.arrive.expect_tx.shared.b64 _, [%0], %1;" \
        :: "r"((uint32_t)(mbar)), "r"((uint32_t)(bytes)) : "memory")
#define MBARRIER_WAIT_PARITY(mbar, parity) do { \
    uint32_t _mbar = (uint32_t)(mbar); \
    uint32_t _par = (uint32_t)(parity); \
    uint32_t _done; \
    asm volatile( \
        "{\n\t.reg .pred p;\n\t" \
        "mbarrier.try_wait.parity.acquire.cta.shared::cta.b64 p, [%1], %2;\n\t" \
        "selp.b32 %0, 1, 0, p;\n\t}" \
        : "=r"(_done) : "r"(_mbar), "r"(_par) : "memory"); \
    if (!_done) { \
        asm volatile( \
            "{\n\t.reg .pred P1;\n\t" \
            "WAIT_LOOP_%=:\n\t" \
            "mbarrier.try_wait.parity.acquire.cta.shared::cta.b64 P1, [%0], %1, 0x989680;\n\t" \
            "@P1 bra.uni WAIT_DONE_%=;\n\t" \
            "bra.uni WAIT_LOOP_%=;\n\t" \
            "WAIT_DONE_%=:\n\t}" \
            :: "r"(_mbar), "r"(_par) : "memory"); \
    } \
} while (0)
#define TMA_LOAD_2D(smem_addr, map_ptr, cx, cy, mbar) \
    asm volatile( \
        "cp.async.bulk.tensor.2d.shared::cta.global.tile.mbarrier::complete_tx::bytes " \
        "[%0], [%1, {%2, %3}], [%4];" \
        :: "r"((uint32_t)(smem_addr)), "l"(map_ptr), \
           "r"((int32_t)(cx)), "r"((int32_t)(cy)), "r"((uint32_t)(mbar)) \
        : "memory")

__device__ __forceinline__ float2 lds64f(uint32_t a) {
    float2 v;
    asm volatile("ld.shared.v2.f32 {%0,%1}, [%2];" : "=f"(v.x), "=f"(v.y) : "r"(a));
    return v;
}
__device__ __forceinline__ void ldsm_x4(uint32_t* r, uint32_t addr) {
    asm volatile("ldmatrix.sync.aligned.m8n8.x4.shared.b16 {%0,%1,%2,%3}, [%4];"
                 : "=r"(r[0]), "=r"(r[1]), "=r"(r[2]), "=r"(r[3]) : "r"(addr));
}
__device__ __forceinline__ uint32_t packh2(float lo, float hi) {
    uint32_t d;
    asm("cvt.rn.f16x2.f32 %0, %1, %2;" : "=r"(d) : "f"(hi), "f"(lo));
    return d;
}
__device__ __forceinline__ void mma16816(float* c, const uint32_t* a,
                                         const uint32_t* b) {
    asm volatile(
        "mma.sync.aligned.m16n8k16.row.col.f32.f16.f16.f32 "
        "{%0,%1,%2,%3}, {%4,%5,%6,%7}, {%8,%9}, {%0,%1,%2,%3};"
        : "+f"(c[0]), "+f"(c[1]), "+f"(c[2]), "+f"(c[3])
        : "r"(a[0]), "r"(a[1]), "r"(a[2]), "r"(a[3]), "r"(b[0]), "r"(b[1]));
}

// ============================================================================
// prep: W [K=512, M=256] row-major fp32 -> g_Wh [M][K] fp16 (RN)
// ============================================================================
__global__ void prep_wh_kernel(const float* __restrict__ W) {
    int idx = blockIdx.x * blockDim.x + threadIdx.x;
    int k = idx >> 8;
    int m = idx & 255;
    g_Wh[m * K_DIM + k] = __float2half_rn(W[idx]);
}

// ============================================================================
// fused GEMM (TMA + register-convert A frags + ldmatrix B + mma.sync) + attn
// ============================================================================
__global__ void __launch_bounds__(THREADS, 3) gat_kernel(
    const __grid_constant__ CUtensorMap tmap_a,
    const __grid_constant__ CUtensorMap tmap_b,
    const int* __restrict__ adj,
    float* __restrict__ out)
{
    extern __shared__ char smem[];
    const uint32_t sb = smem_u32(smem);
    uint32_t* smask = (uint32_t*)(smem + MASK_OFF);   // [64][8]
    int* scnt = (int*)(smem + CNT_OFF);               // [64][2]

    const int tid  = threadIdx.x;
    const int lane = tid & 31;
    const int wn   = tid >> 5;   // 0..3 : 64-col band (single m-band)
    const int tile = blockIdx.x * BM;

    // ---- mbarrier init + TMA prologue -----------------------------------------
    if (tid == 0) {
        MBARRIER_INIT(sb + MBAR_A(0), 1);
        MBARRIER_INIT(sb + MBAR_A(1), 1);
        MBARRIER_INIT(sb + MBAR_A(2), 1);
        MBARRIER_INIT(sb + MBAR_B(0), 1);
        MBARRIER_INIT(sb + MBAR_B(1), 1);
    }
    __syncthreads();
    if (tid == 0) {
        #pragma unroll
        for (int j = 0; j < 3; j++) {
            MBARRIER_EXPECT_TX(sb + MBAR_A(j), TXA);
            TMA_LOAD_2D(sb + A32_OFF(j), &tmap_a, j * BK, tile, sb + MBAR_A(j));
        }
        #pragma unroll
        for (int j = 0; j < 2; j++) {
            MBARRIER_EXPECT_TX(sb + MBAR_B(j), TXB);
            TMA_LOAD_2D(sb + B_OFF(j), &tmap_b, j * BK, 0, sb + MBAR_B(j));
        }
    }

    // ---- adj mask + count (overlaps TMA flight; 64 | N_ROWS) -------------------
    {
        int r = tid >> 1;            // 0..63
        int h = tid & 1;             // 128-col half
        const int4* ap = (const int4*)(adj + (size_t)(tile + r) * M_DIM + h * 128);
        int cnt = 0;
        #pragma unroll
        for (int g = 0; g < 4; g++) {
            uint32_t m = 0;
            #pragma unroll
            for (int w = 0; w < 8; w++) {
                int4 v = __ldg(ap + g * 8 + w);
                m |= (v.x > 0 ? 1u : 0u) << (w * 4 + 0);
                m |= (v.y > 0 ? 1u : 0u) << (w * 4 + 1);
                m |= (v.z > 0 ? 1u : 0u) << (w * 4 + 2);
                m |= (v.w > 0 ? 1u : 0u) << (w * 4 + 3);
            }
            smask[r * 8 + h * 4 + g] = m;
            cnt += __popc(m);
        }
        scnt[r * 2 + h] = cnt;
    }

    // ---- per-thread constants ----------------------------------------------------
    const int arow = lane >> 2;                 // 0..7 (mma row group / epilogue)

    // A-frag LDS.64 addressing in the SW128 fp32 tile:
    //   element (row, k) at row*128 + (k*4 ^ ((row&7)<<4));
    //   frag rows: mf*16 + arow (+8); k pairs at ks*16 + (lane&3)*2 (+8).
    const uint32_t xorA = (uint32_t)arow << 4;          // (row&7) == arow for all frag rows
    const uint32_t cb   = (uint32_t)(lane & 3) * 8;     // k-pair byte offset
    const uint32_t offA[4] = {                          // [ks][sigma]
        (cb)       ^ xorA, (cb + 32)       ^ xorA,      // ks=0: k, k+8
        (cb + 64)  ^ xorA, (cb + 96)       ^ xorA       // ks=1
    };
    const uint32_t a_row_b = (uint32_t)arow * 128;      // + A32_OFF(s)

    // B ldmatrix addressing (SW64: unit ^= (row>>1)&3) — unchanged from R11
    const uint32_t l7 = lane & 7;
    const uint32_t sw64x = ((l7 >> 1) & 3) << 4;
    const uint32_t b_row = (uint32_t)(wn * 64) + l7 + ((lane >> 4) & 1) * 8;
    const uint32_t b_kseg = (lane >> 3) & 1;
    const uint32_t b_base_off = b_row * 64;

    float c[4][8][4];
    #pragma unroll
    for (int mf = 0; mf < 4; mf++)
        #pragma unroll
        for (int nf = 0; nf < 8; nf++)
            #pragma unroll
            for (int e = 0; e < 4; e++) c[mf][nf][e] = 0.0f;

    int as = 0, aph = 0;   // A ring cursor (slot = i%3, parity = (i/3)&1)

    // ---- mainloop: 16 x BK=32 -------------------------------------------------------
    #pragma unroll 1
    for (int i = 0; i < NITER; i++) {
        MBARRIER_WAIT_PARITY(sb + MBAR_A(as), (uint32_t)aph);
        MBARRIER_WAIT_PARITY(sb + MBAR_B(i & 1), (uint32_t)((i >> 1) & 1));
        {
            const uint32_t aS = sb + A32_OFF(as) + a_row_b;
            const uint32_t bB = sb + B_OFF(i & 1) + b_base_off;
            #pragma unroll
            for (int ks = 0; ks < 2; ks++) {
                const uint32_t o0 = offA[ks * 2 + 0];
                const uint32_t o1 = offA[ks * 2 + 1];
                const uint32_t bk = (((uint32_t)ks * 2 + b_kseg) << 4) ^ sw64x;
                uint32_t ra[4][4];
                #pragma unroll
                for (int mf = 0; mf < 4; mf++) {
                    const uint32_t rb_ = aS + (uint32_t)mf * 2048;
                    float2 x0 = lds64f(rb_ + o0);
                    float2 x1 = lds64f(rb_ + 1024 + o0);
                    float2 x2 = lds64f(rb_ + o1);
                    float2 x3 = lds64f(rb_ + 1024 + o1);
                    ra[mf][0] = packh2(x0.x, x0.y);
                    ra[mf][1] = packh2(x1.x, x1.y);
                    ra[mf][2] = packh2(x2.x, x2.y);
                    ra[mf][3] = packh2(x3.x, x3.y);
                }
                #pragma unroll
                for (int np = 0; np < 4; np++) {
                    uint32_t rb[4];
                    ldsm_x4(rb, bB + (uint32_t)np * 1024 + bk);
                    #pragma unroll
                    for (int mf = 0; mf < 4; mf++) {
                        mma16816(c[mf][np * 2 + 0], ra[mf], rb);
                        mma16816(c[mf][np * 2 + 1], ra[mf], rb + 2);
                    }
                }
            }
        }
        __syncthreads();   // all warps done reading A32[as] + B[i&1]

        // refills: A chunk i+3 into the slot just freed, B chunk i+2 likewise
        if (tid == 0) {
            if (i + 3 < NITER) {
                MBARRIER_EXPECT_TX(sb + MBAR_A(as), TXA);
                TMA_LOAD_2D(sb + A32_OFF(as), &tmap_a, (i + 3) * BK, tile,
                            sb + MBAR_A(as));
            }
            if (i + 2 < NITER) {
                MBARRIER_EXPECT_TX(sb + MBAR_B(i & 1), TXB);
                TMA_LOAD_2D(sb + B_OFF(i & 1), &tmap_b, (i + 2) * BK, 0,
                            sb + MBAR_B(i & 1));
            }
        }
        if (++as == 3) { as = 0; aph ^= 1; }
    }

    // ---- epilogue: scale by 1/cnt on mask, elu, store -------------------------------
    #pragma unroll
    for (int mf = 0; mf < 4; mf++) {
        const int r0 = mf * 16 + arow;
        #pragma unroll
        for (int half = 0; half < 2; half++) {
            const int rr = r0 + half * 8;
            const int grow = tile + rr;
            const int cnt = scnt[rr * 2] + scnt[rr * 2 + 1];
            const bool all_on = (cnt == 0);
            const float scale = all_on ? (1.0f / 256.0f) : (1.0f / (float)cnt);
            #pragma unroll
            for (int nf = 0; nf < 8; nf++) {
                const int col = wn * 64 + nf * 8 + (int)(lane & 3) * 2;
                const uint32_t mw = smask[rr * 8 + (col >> 5)];
                float2 o;
                #pragma unroll
                for (int e = 0; e < 2; e++) {
                    float h = c[mf][nf][half * 2 + e];
                    bool on = all_on | (((mw >> ((col + e) & 31)) & 1u) != 0u);
                    float v = on ? h * scale : 0.0f;
                    float res = (v > 0.0f) ? v : (__expf(v) - 1.0f);
                    ((float*)&o)[e] = res;
                }
                *(float2*)(out + (size_t)grow * M_DIM + col) = o;
            }
        }
    }
}

// ============================================================================
// host launch
// ============================================================================
typedef CUresult (*EncodeTiledFn)(
    CUtensorMap*, CUtensorMapDataType, cuuint32_t, void*,
    const cuuint64_t*, const cuuint64_t*, const cuuint32_t*, const cuuint32_t*,
    CUtensorMapInterleave, CUtensorMapSwizzle, CUtensorMapL2promotion,
    CUtensorMapFloatOOBfill);

extern "C" void kernel_launch(void* const* d_in, const int* in_sizes, int n_in,
                              void* d_out, int out_size) {
    const float* inp = (const float*)d_in[0];
    const int*   adj = (const int*)d_in[1];
    const float* W   = (const float*)d_in[2];
    // d_in[3] ('a') provably cancels in the softmax; unused.
    float* out = (float*)d_out;

    prep_wh_kernel<<<(K_DIM * M_DIM) / 256, 256>>>(W);

    void* wh_ptr = nullptr;
    cudaGetSymbolAddress(&wh_ptr, g_Wh);

    void* fp = nullptr;
    cudaDriverEntryPointQueryResult qres;
    cudaGetDriverEntryPointByVersion("cuTensorMapEncodeTiled", &fp, 12000,
                                     cudaEnableDefault, &qres);
    EncodeTiledFn enc = (EncodeTiledFn)fp;

    alignas(64) CUtensorMap tmA;
    alignas(64) CUtensorMap tmB;
    {
        cuuint64_t dims[2]    = {(cuuint64_t)K_DIM, (cuuint64_t)N_ROWS};
        cuuint64_t strides[1] = {(cuuint64_t)K_DIM * sizeof(float)};
        cuuint32_t box[2]     = {32u, (cuuint32_t)BM};      // 128B x 64 rows
        cuuint32_t es[2]      = {1, 1};
        enc(&tmA, CU_TENSOR_MAP_DATA_TYPE_FLOAT32, 2, (void*)inp,
            dims, strides, box, es,
            CU_TENSOR_MAP_INTERLEAVE_NONE, CU_TENSOR_MAP_SWIZZLE_128B,
            CU_TENSOR_MAP_L2_PROMOTION_L2_128B, CU_TENSOR_MAP_FLOAT_OOB_FILL_NONE);
    }
    {
        cuuint64_t dims[2]    = {(cuuint64_t)K_DIM, (cuuint64_t)M_DIM};
        cuuint64_t strides[1] = {(cuuint64_t)K_DIM * sizeof(__half)};
        cuuint32_t box[2]     = {32u, (cuuint32_t)M_DIM};   // 64B x 256 rows
        cuuint32_t es[2]      = {1, 1};
        enc(&tmB, CU_TENSOR_MAP_DATA_TYPE_FLOAT16, 2, wh_ptr,
            dims, strides, box, es,
            CU_TENSOR_MAP_INTERLEAVE_NONE, CU_TENSOR_MAP_SWIZZLE_64B,
            CU_TENSOR_MAP_L2_PROMOTION_L2_128B, CU_TENSOR_MAP_FLOAT_OOB_FILL_NONE);
    }

    static bool attr_set = false;
    if (!attr_set) {
        cudaFuncSetAttribute(gat_kernel,
                             cudaFuncAttributeMaxDynamicSharedMemorySize,
                             SMEM_TOTAL);
        attr_set = true;
    }
    const int grid = N_ROWS / BM;   // 3125 (exact)
    gat_kernel<<<grid, THREADS, SMEM_TOTAL>>>(tmA, tmB, adj, out);
}

// round 15
// speedup vs baseline: 1.2539x; 1.1718x over previous
#include <cuda.h>
#include <cuda_runtime.h>
#include <cuda_fp16.h>
#include <cstdint>

// ============================================================================
// out = elu( (adj>0 ? (input@W)/cnt_row : 0) ), cnt_row = #(adj>0 in row);
// cnt==0 rows: softmax of all-(-9e15) is uniform 1/256.
// R15: R12/R13/R14 all regressed -> R11 (203us) pipeline is locally optimal.
//      This is R11 EXACTLY, plus: fully unrolled mainloop (slots/phases become
//      immediates; alu was 20.9%) and st.global.cs output stores (evict-first,
//      protect L2-resident W). No structural changes.
// ============================================================================

#define N_ROWS 200000
#define K_DIM  512
#define M_DIM  256
#define BM     64
#define BK     32
#define NITER  (K_DIM / BK)     // 16
#define THREADS 128             // 4 warps: 1 (m) x 4 (n), warp tile 64x64

// --- shared memory layout (bytes) --------------------------------------------
#define MBAR_A(s)  ((s) * 8)            // 0, 8, 16
#define MBAR_B(s)  (24 + (s) * 8)       // 24, 32
#define MBAR_FD    40                   // frag-done, count 128
#define MASK_OFF   128                  // u32[64][8] -> 2176
#define CNT_OFF    (MASK_OFF + 64 * 8 * 4)      // int[64][2] -> 2688
#define A16_OFF    4096                 // 4KB (64 x 64B rows, SW64)
#define A32_OFF(s) (8192 + (s) * 8192)  // 3 x 8KB (64 x 128B rows, SW128)
#define B_OFF(s)   (32768 + (s) * 16384) // 2 x 16KB (256 x 64B rows, SW64)
#define SMEM_TOTAL 65536                // 64KB -> 3 CTAs/SM
#define TXA        8192
#define TXB        16384

// --- device scratch: W transposed to [M][K], fp16 RN --------------------------
__device__ __half g_Wh[M_DIM * K_DIM];

// ============================================================================
// helpers (plain sm_90-level PTX; no 'a' features)
// ============================================================================
__device__ __forceinline__ uint32_t smem_u32(const void* p) {
    uint32_t a;
    asm("{ .reg .u64 t; cvta.to.shared.u64 t, %1; cvt.u32.u64 %0, t; }"
        : "=r"(a) : "l"(p));
    return a;
}
#define MBARRIER_INIT(mbar, count) \
    asm volatile("mbarrier.init.shared.b64 [%0], %1;" \
        :: "r"((uint32_t)(mbar)), "r"((uint32_t)(count)) : "memory")
#define MBARRIER_EXPECT_TX(mbar, bytes) \
    asm volatile("mbarrier.arrive.expect_tx.shared.b64 _, [%0], %1;" \
        :: "r"((uint32_t)(mbar)), "r"((uint32_t)(bytes)) : "memory")
#define MBARRIER_ARRIVE(mbar) \
    asm volatile("mbarrier.arrive.release.cta.shared.b64 _, [%0];" \
        :: "r"((uint32_t)(mbar)) : "memory")
#define MBARRIER_WAIT_PARITY(mbar, parity) do { \
    uint32_t _mbar = (uint32_t)(mbar); \
    uint32_t _par = (uint32_t)(parity); \
    uint32_t _done; \
    asm volatile( \
        "{\n\t.reg .pred p;\n\t" \
        "mbarrier.try_wait.parity.acquire.cta.shared::cta.b64 p, [%1], %2;\n\t" \
        "selp.b32 %0, 1, 0, p;\n\t}" \
        : "=r"(_done) : "r"(_mbar), "r"(_par) : "memory"); \
    if (!_done) { \
        asm volatile( \
            "{\n\t.reg .pred P1;\n\t" \
            "WAIT_LOOP_%=:\n\t" \
            "mbarrier.try_wait.parity.acquire.cta.shared::cta.b64 P1, [%0], %1, 0x989680;\n\t" \
            "@P1 bra.uni WAIT_DONE_%=;\n\t" \
            "bra.uni WAIT_LOOP_%=;\n\t" \
            "WAIT_DONE_%=:\n\t}" \
            :: "r"(_mbar), "r"(_par) : "memory"); \
    } \
} while (0)
#define TMA_LOAD_2D(smem_addr, map_ptr, cx, cy, mbar) \
    asm volatile( \
        "cp.async.bulk.tensor.2d.shared::cta.global.tile.mbarrier::complete_tx::bytes " \
        "[%0], [%1, {%2, %3}], [%4];" \
        :: "r"((uint32_t)(smem_addr)), "l"(map_ptr), \
           "r"((int32_t)(cx)), "r"((int32_t)(cy)), "r"((uint32_t)(mbar)) \
        : "memory")

__device__ __forceinline__ float4 lds128f(uint32_t a) {
    float4 v;
    asm volatile("ld.shared.v4.f32 {%0,%1,%2,%3}, [%4];"
                 : "=f"(v.x), "=f"(v.y), "=f"(v.z), "=f"(v.w) : "r"(a));
    return v;
}
__device__ __forceinline__ void sts128(uint32_t a, uint32_t r0, uint32_t r1,
                                       uint32_t r2, uint32_t r3) {
    asm volatile("st.shared.v4.b32 [%0], {%1,%2,%3,%4};"
                 :: "r"(a), "r"(r0), "r"(r1), "r"(r2), "r"(r3) : "memory");
}
__device__ __forceinline__ void ldsm_x4(uint32_t* r, uint32_t addr) {
    asm volatile("ldmatrix.sync.aligned.m8n8.x4.shared.b16 {%0,%1,%2,%3}, [%4];"
                 : "=r"(r[0]), "=r"(r[1]), "=r"(r[2]), "=r"(r[3]) : "r"(addr));
}
__device__ __forceinline__ uint32_t packh2(float lo, float hi) {
    uint32_t d;
    asm("cvt.rn.f16x2.f32 %0, %1, %2;" : "=r"(d) : "f"(hi), "f"(lo));
    return d;
}
__device__ __forceinline__ void mma16816(float* c, const uint32_t* a,
                                         const uint32_t* b) {
    asm volatile(
        "mma.sync.aligned.m16n8k16.row.col.f32.f16.f16.f32 "
        "{%0,%1,%2,%3}, {%4,%5,%6,%7}, {%8,%9}, {%0,%1,%2,%3};"
        : "+f"(c[0]), "+f"(c[1]), "+f"(c[2]), "+f"(c[3])
        : "r"(a[0]), "r"(a[1]), "r"(a[2]), "r"(a[3]), "r"(b[0]), "r"(b[1]));
}
__device__ __forceinline__ void stg_cs_v2(float* p, float x, float y) {
    asm volatile("st.global.cs.v2.f32 [%0], {%1,%2};"
                 :: "l"(p), "f"(x), "f"(y) : "memory");
}

// ============================================================================
// prep: W [K=512, M=256] row-major fp32 -> g_Wh [M][K] fp16 (RN)
// ============================================================================
__global__ void prep_wh_kernel(const float* __restrict__ W) {
    int idx = blockIdx.x * blockDim.x + threadIdx.x;
    int k = idx >> 8;
    int m = idx & 255;
    g_Wh[m * K_DIM + k] = __float2half_rn(W[idx]);
}

// ============================================================================
// fused GEMM (TMA + split-phase convert + ldmatrix + mma.sync) + attention
// ============================================================================
__global__ void __launch_bounds__(THREADS, 3) gat_kernel(
    const __grid_constant__ CUtensorMap tmap_a,
    const __grid_constant__ CUtensorMap tmap_b,
    const int* __restrict__ adj,
    float* __restrict__ out)
{
    extern __shared__ char smem[];
    const uint32_t sb = smem_u32(smem);
    uint32_t* smask = (uint32_t*)(smem + MASK_OFF);   // [64][8]
    int* scnt = (int*)(smem + CNT_OFF);               // [64][2]

    const int tid  = threadIdx.x;
    const int lane = tid & 31;
    const int wn   = tid >> 5;   // 0..3 : 64-col band (single m-band)
    const int tile = blockIdx.x * BM;

    // ---- mbarrier init + TMA prologue -----------------------------------------
    if (tid == 0) {
        MBARRIER_INIT(sb + MBAR_A(0), 1);
        MBARRIER_INIT(sb + MBAR_A(1), 1);
        MBARRIER_INIT(sb + MBAR_A(2), 1);
        MBARRIER_INIT(sb + MBAR_B(0), 1);
        MBARRIER_INIT(sb + MBAR_B(1), 1);
        MBARRIER_INIT(sb + MBAR_FD, THREADS);
    }
    __syncthreads();
    if (tid == 0) {
        #pragma unroll
        for (int j = 0; j < 3; j++) {
            MBARRIER_EXPECT_TX(sb + MBAR_A(j), TXA);
            TMA_LOAD_2D(sb + A32_OFF(j), &tmap_a, j * BK, tile, sb + MBAR_A(j));
        }
        #pragma unroll
        for (int j = 0; j < 2; j++) {
            MBARRIER_EXPECT_TX(sb + MBAR_B(j), TXB);
            TMA_LOAD_2D(sb + B_OFF(j), &tmap_b, j * BK, 0, sb + MBAR_B(j));
        }
    }

    // ---- adj mask + count (overlaps TMA flight; 64 | N_ROWS) -------------------
    {
        int r = tid >> 1;            // 0..63
        int h = tid & 1;             // 128-col half
        const int4* ap = (const int4*)(adj + (size_t)(tile + r) * M_DIM + h * 128);
        int cnt = 0;
        #pragma unroll
        for (int g = 0; g < 4; g++) {
            uint32_t m = 0;
            #pragma unroll
            for (int w = 0; w < 8; w++) {
                int4 v = __ldg(ap + g * 8 + w);
                m |= (v.x > 0 ? 1u : 0u) << (w * 4 + 0);
                m |= (v.y > 0 ? 1u : 0u) << (w * 4 + 1);
                m |= (v.z > 0 ? 1u : 0u) << (w * 4 + 2);
                m |= (v.w > 0 ? 1u : 0u) << (w * 4 + 3);
            }
            smask[r * 8 + h * 4 + g] = m;
            cnt += __popc(m);
        }
        scnt[r * 2 + h] = cnt;
    }

    // ---- per-thread constants ----------------------------------------------------
    const int arow = lane >> 2;                 // 0..7 (epilogue)

    // convert mapping: row cr = tid>>1 (0..63), k-half sub = tid&1
    const int cr  = tid >> 1;
    const int sub = tid & 1;
    const uint32_t xr128 = (uint32_t)(cr & 7) << 4;        // src SW128 xor
    const uint32_t xr64  = (uint32_t)((cr >> 1) & 3) << 4; // dst SW64 xor
    const uint32_t csrc_row = (uint32_t)cr * 128;          // + A32_OFF(slot)
    const uint32_t csu = (uint32_t)sub * 4;                // src 16B-unit base
    const uint32_t cdst = sb + A16_OFF + (uint32_t)cr * 64;
    const uint32_t cdu = (uint32_t)sub * 2;                // dst 16B-unit base

    // ldmatrix lane addressing (SW64: unit ^= (row>>1)&3)
    const uint32_t l7 = lane & 7;
    const uint32_t sw64x = ((l7 >> 1) & 3) << 4;
    const uint32_t a_row = l7 + ((lane >> 3) & 1) * 8;
    const uint32_t a_kseg = (lane >> 4) & 1;
    const uint32_t a_base = sb + A16_OFF + a_row * 64;
    const uint32_t b_row = (uint32_t)(wn * 64) + l7 + ((lane >> 4) & 1) * 8;
    const uint32_t b_kseg = (lane >> 3) & 1;
    const uint32_t b_base_off = b_row * 64;

    float c[4][8][4];
    #pragma unroll
    for (int mf = 0; mf < 4; mf++)
        #pragma unroll
        for (int nf = 0; nf < 8; nf++)
            #pragma unroll
            for (int e = 0; e < 4; e++) c[mf][nf][e] = 0.0f;

    // ---- prologue convert: chunk 0 -> A16 ----------------------------------------
    MBARRIER_WAIT_PARITY(sb + MBAR_A(0), 0);
    {
        const uint32_t src = sb + A32_OFF(0) + csrc_row;
        float4 f0 = lds128f(src + (((csu + 0) << 4) ^ xr128));
        float4 f1 = lds128f(src + (((csu + 1) << 4) ^ xr128));
        float4 f2 = lds128f(src + (((csu + 2) << 4) ^ xr128));
        float4 f3 = lds128f(src + (((csu + 3) << 4) ^ xr128));
        sts128(cdst + (((cdu + 0) << 4) ^ xr64),
               packh2(f0.x, f0.y), packh2(f0.z, f0.w),
               packh2(f1.x, f1.y), packh2(f1.z, f1.w));
        sts128(cdst + (((cdu + 1) << 4) ^ xr64),
               packh2(f2.x, f2.y), packh2(f2.z, f2.w),
               packh2(f3.x, f3.y), packh2(f3.z, f3.w));
    }
    __syncthreads();   // A16(chunk0) visible

    // ---- mainloop: 16 x BK=32, FULLY UNROLLED (slots/phases are immediates) -------
    #pragma unroll
    for (int i = 0; i < NITER; i++) {
        // phase 1: MMAs on chunk i
        MBARRIER_WAIT_PARITY(sb + MBAR_B(i & 1), (uint32_t)((i >> 1) & 1));
        {
            const uint32_t bB = sb + B_OFF(i & 1) + b_base_off;
            #pragma unroll
            for (int ks = 0; ks < 2; ks++) {
                const uint32_t ak = (((uint32_t)ks * 2 + a_kseg) << 4) ^ sw64x;
                const uint32_t bk = (((uint32_t)ks * 2 + b_kseg) << 4) ^ sw64x;
                uint32_t ra[4][4];
                #pragma unroll
                for (int mf = 0; mf < 4; mf++)
                    ldsm_x4(ra[mf], a_base + (uint32_t)mf * 1024 + ak);
                #pragma unroll
                for (int np = 0; np < 4; np++) {
                    uint32_t rb[4];
                    ldsm_x4(rb, bB + (uint32_t)np * 1024 + bk);
                    #pragma unroll
                    for (int mf = 0; mf < 4; mf++) {
                        mma16816(c[mf][np * 2 + 0], ra[mf], rb);
                        mma16816(c[mf][np * 2 + 1], ra[mf], rb + 2);
                    }
                }
            }
        }
        MBARRIER_ARRIVE(sb + MBAR_FD);   // my A16 + B[i&1] reads complete

        // phase 2: convert chunk i+1 (LDS+cvt BEFORE the FD wait -> overlap)
        if (i + 1 < NITER) {
            const int sl = (i + 1) % 3;                   // compile-time
            const uint32_t ph = (uint32_t)(((i + 1) / 3) & 1);
            MBARRIER_WAIT_PARITY(sb + MBAR_A(sl), ph);
            const uint32_t src = sb + A32_OFF(sl) + csrc_row;
            float4 f0 = lds128f(src + (((csu + 0) << 4) ^ xr128));
            float4 f1 = lds128f(src + (((csu + 1) << 4) ^ xr128));
            float4 f2 = lds128f(src + (((csu + 2) << 4) ^ xr128));
            float4 f3 = lds128f(src + (((csu + 3) << 4) ^ xr128));
            uint32_t h0 = packh2(f0.x, f0.y), h1 = packh2(f0.z, f0.w);
            uint32_t h2 = packh2(f1.x, f1.y), h3 = packh2(f1.z, f1.w);
            uint32_t h4 = packh2(f2.x, f2.y), h5 = packh2(f2.z, f2.w);
            uint32_t h6 = packh2(f3.x, f3.y), h7 = packh2(f3.z, f3.w);
            // wait all CTA threads finished reading A16(chunk i)
            MBARRIER_WAIT_PARITY(sb + MBAR_FD, (uint32_t)(i & 1));
            sts128(cdst + (((cdu + 0) << 4) ^ xr64), h0, h1, h2, h3);
            sts128(cdst + (((cdu + 1) << 4) ^ xr64), h4, h5, h6, h7);
        }
        __syncthreads();   // A16(chunk i+1) visible; A32[(i+1)%3] + B[i&1] free

        // refills: A chunk i+3 into slot i%3, B chunk i+2 into slot i&1
        if (tid == 0) {
            if (i + 3 < NITER) {
                const int rs = i % 3;                     // compile-time
                MBARRIER_EXPECT_TX(sb + MBAR_A(rs), TXA);
                TMA_LOAD_2D(sb + A32_OFF(rs), &tmap_a, (i + 3) * BK, tile,
                            sb + MBAR_A(rs));
            }
            if (i + 2 < NITER) {
                MBARRIER_EXPECT_TX(sb + MBAR_B(i & 1), TXB);
                TMA_LOAD_2D(sb + B_OFF(i & 1), &tmap_b, (i + 2) * BK, 0,
                            sb + MBAR_B(i & 1));
            }
        }
    }

    // ---- epilogue: scale by 1/cnt on mask, elu, streaming store -------------------
    #pragma unroll
    for (int mf = 0; mf < 4; mf++) {
        const int r0 = mf * 16 + arow;
        #pragma unroll
        for (int half = 0; half < 2; half++) {
            const int rr = r0 + half * 8;
            const int grow = tile + rr;
            const int cnt = scnt[rr * 2] + scnt[rr * 2 + 1];
            const bool all_on = (cnt == 0);
            const float scale = all_on ? (1.0f / 256.0f) : (1.0f / (float)cnt);
            #pragma unroll
            for (int nf = 0; nf < 8; nf++) {
                const int col = wn * 64 + nf * 8 + (int)(lane & 3) * 2;
                const uint32_t mw = smask[rr * 8 + (col >> 5)];
                float o[2];
                #pragma unroll
                for (int e = 0; e < 2; e++) {
                    float h = c[mf][nf][half * 2 + e];
                    bool on = all_on | (((mw >> ((col + e) & 31)) & 1u) != 0u);
                    float v = on ? h * scale : 0.0f;
                    o[e] = (v > 0.0f) ? v : (__expf(v) - 1.0f);
                }
                stg_cs_v2(out + (size_t)grow * M_DIM + col, o[0], o[1]);
            }
        }
    }
}

// ============================================================================
// host launch
// ============================================================================
typedef CUresult (*EncodeTiledFn)(
    CUtensorMap*, CUtensorMapDataType, cuuint32_t, void*,
    const cuuint64_t*, const cuuint64_t*, const cuuint32_t*, const cuuint32_t*,
    CUtensorMapInterleave, CUtensorMapSwizzle, CUtensorMapL2promotion,
    CUtensorMapFloatOOBfill);

extern "C" void kernel_launch(void* const* d_in, const int* in_sizes, int n_in,
                              void* d_out, int out_size) {
    const float* inp = (const float*)d_in[0];
    const int*   adj = (const int*)d_in[1];
    const float* W   = (const float*)d_in[2];
    // d_in[3] ('a') provably cancels in the softmax; unused.
    float* out = (float*)d_out;

    prep_wh_kernel<<<(K_DIM * M_DIM) / 256, 256>>>(W);

    void* wh_ptr = nullptr;
    cudaGetSymbolAddress(&wh_ptr, g_Wh);

    void* fp = nullptr;
    cudaDriverEntryPointQueryResult qres;
    cudaGetDriverEntryPointByVersion("cuTensorMapEncodeTiled", &fp, 12000,
                                     cudaEnableDefault, &qres);
    EncodeTiledFn enc = (EncodeTiledFn)fp;

    alignas(64) CUtensorMap tmA;
    alignas(64) CUtensorMap tmB;
    {
        cuuint64_t dims[2]    = {(cuuint64_t)K_DIM, (cuuint64_t)N_ROWS};
        cuuint64_t strides[1] = {(cuuint64_t)K_DIM * sizeof(float)};
        cuuint32_t box[2]     = {32u, (cuuint32_t)BM};      // 128B x 64 rows
        cuuint32_t es[2]      = {1, 1};
        enc(&tmA, CU_TENSOR_MAP_DATA_TYPE_FLOAT32, 2, (void*)inp,
            dims, strides, box, es,
            CU_TENSOR_MAP_INTERLEAVE_NONE, CU_TENSOR_MAP_SWIZZLE_128B,
            CU_TENSOR_MAP_L2_PROMOTION_L2_128B, CU_TENSOR_MAP_FLOAT_OOB_FILL_NONE);
    }
    {
        cuuint64_t dims[2]    = {(cuuint64_t)K_DIM, (cuuint64_t)M_DIM};
        cuuint64_t strides[1] = {(cuuint64_t)K_DIM * sizeof(__half)};
        cuuint32_t box[2]     = {32u, (cuuint32_t)M_DIM};   // 64B x 256 rows
        cuuint32_t es[2]      = {1, 1};
        enc(&tmB, CU_TENSOR_MAP_DATA_TYPE_FLOAT16, 2, wh_ptr,
            dims, strides, box, es,
            CU_TENSOR_MAP_INTERLEAVE_NONE, CU_TENSOR_MAP_SWIZZLE_64B,
            CU_TENSOR_MAP_L2_PROMOTION_L2_128B, CU_TENSOR_MAP_FLOAT_OOB_FILL_NONE);
    }

    static bool attr_set = false;
    if (!attr_set) {
        cudaFuncSetAttribute(gat_kernel,
                             cudaFuncAttributeMaxDynamicSharedMemorySize,
                             SMEM_TOTAL);
        attr_set = true;
    }
    const int grid = N_ROWS / BM;   // 3125 (exact)
    gat_kernel<<<grid, THREADS, SMEM_TOTAL>>>(tmA, tmB, adj, out);
}